// round 17
// baseline (speedup 1.0000x reference)
#include <cuda_runtime.h>
#include <math.h>
#include <stdint.h>

#define T     128
#define H     1024
#define INTER 4096
#define NE    8

// ---------------- device-global scratch ----------------
__device__ int   g_cnt[NE];
__device__ int   g_tok[NE][T];
__device__ float g_coef[NE][T];           // pad slots never written -> stay 0
// chunk-packed tf32-rounded fp32 activations: [e][k-chunk32][m][32 k]
__device__ float g_xg[NE][32][T][32];     // gathered token rows (4.2 MB)
__device__ float g_act[NE][128][T][32];   // coef-scaled swiglu output (16.8 MB)

// ---------------- smem layout (dynamic) ----------------
// [0,512) coefs/toks
// stages: 3 x 24KB = [A0 4KB][A1 4KB][B0 8KB][B1 8KB]; fp32, 128B rows per
// sub-block, 16B unit u of row r stored at u ^ (r & 7). K-chunk = 64 floats
// (two 32-float sub-chunks) -> every DRAM row-visit reads 256B contiguous.
#define ST_OFF   1024
#define STAGEB   24576
#define SMEM_BYTES (1024 + 3 * STAGEB)   // 74752

// ---------------- PTX helpers ----------------
static __device__ __forceinline__ uint32_t smem_u32(const void* p){
    uint32_t a;
    asm("{ .reg .u64 t; cvta.to.shared.u64 t, %1; cvt.u32.u64 %0, t; }" : "=r"(a) : "l"(p));
    return a;
}
#define CP16(d, s)  asm volatile("cp.async.cg.shared.global [%0], [%1], 16;" :: "r"(d), "l"(s) : "memory")
#define CP_COMMIT() asm volatile("cp.async.commit_group;" ::: "memory")
#define CP_WAIT1()  asm volatile("cp.async.wait_group 1;" ::: "memory")

static __device__ __forceinline__ uint32_t f2tf(float x){
    uint32_t r; asm("cvt.rna.tf32.f32 %0, %1;" : "=r"(r) : "f"(x)); return r;
}
static __device__ __forceinline__ uint32_t rnd_bits(uint32_t b){
    return f2tf(__uint_as_float(b));
}
#define LDM4(r, addr) \
    asm volatile("ldmatrix.sync.aligned.m8n8.x4.shared.b16 {%0,%1,%2,%3}, [%4];" \
        : "=r"((r)[0]), "=r"((r)[1]), "=r"((r)[2]), "=r"((r)[3]) : "r"(addr))

static __device__ __forceinline__ void mma8(float* d, const uint32_t* a, uint32_t b0, uint32_t b1){
    asm volatile("mma.sync.aligned.m16n8k8.row.col.f32.tf32.tf32.f32 "
        "{%0,%1,%2,%3}, {%4,%5,%6,%7}, {%8,%9}, {%0,%1,%2,%3};"
        : "+f"(d[0]), "+f"(d[1]), "+f"(d[2]), "+f"(d[3])
        : "r"(a[0]), "r"(a[1]), "r"(a[2]), "r"(a[3]), "r"(b0), "r"(b1));
}

// ---------------- kernel 1: routing ----------------
__global__ void route_kernel(const float* __restrict__ routing) {
    __shared__ int s_cnt[NE];
    int t = threadIdx.x;
    if (t < NE) s_cnt[t] = 0;
    __syncthreads();
    float r[NE];
#pragma unroll
    for (int e = 0; e < NE; e++) r[e] = routing[t * NE + e];
    int i0 = 0;
#pragma unroll
    for (int e = 1; e < NE; e++) if (r[e] > r[i0]) i0 = e;
    int i1 = (i0 == 0) ? 1 : 0;
#pragma unroll
    for (int e = 0; e < NE; e++) if (e != i0 && r[e] > r[i1]) i1 = e;
    float d  = expf(r[i1] - r[i0]);
    float s0 = 1.0f / (1.0f + d);
    float s1 = d / (1.0f + d);
    int p0 = atomicAdd(&s_cnt[i0], 1);
    int p1 = atomicAdd(&s_cnt[i1], 1);
    g_tok[i0][p0] = t;  g_coef[i0][p0] = s0;
    g_tok[i1][p1] = t;  g_coef[i1][p1] = s1;
    __syncthreads();
    if (t < NE) g_cnt[t] = s_cnt[t];
}

// ---------------- kernel 2: gather token rows (tf32-rounded, chunk-packed) + zero out ----
__global__ void gather_x_kernel(const float* __restrict__ x, float* __restrict__ out) {
    int bid = blockIdx.x;
    int e = bid >> 7, m = bid & 127;
    int t = threadIdx.x;
    out[bid * 128 + t] = 0.0f;
    int tok = (m < g_cnt[e]) ? g_tok[e][m] : 0;
    const float4* src = (const float4*)(x + (size_t)tok * H);
    float4 v0 = src[2 * t];
    float4 v1 = src[2 * t + 1];
    uint4 o0, o1;
    o0.x = f2tf(v0.x); o0.y = f2tf(v0.y); o0.z = f2tf(v0.z); o0.w = f2tf(v0.w);
    o1.x = f2tf(v1.x); o1.y = f2tf(v1.y); o1.z = f2tf(v1.z); o1.w = f2tf(v1.w);
    uint4* dst = (uint4*)&g_xg[e][t >> 2][m][(t & 3) * 8];
    dst[0] = o0; dst[1] = o1;
}

// ================= GEMM machinery =================
// CTA tile M=32 x N=64 x Kchunk=64 (8 tf32 k8 steps); 8 warps as 2(M) x 4(N),
// warp tile 16x16. A pre-rounded; B rounded in fragments (bit-identical math).
static __device__ __forceinline__ void compute_chunk(
        uint32_t aAf, uint32_t aBf, float (&acc)[2][4]) {
#pragma unroll
    for (int ks = 0; ks < 8; ks++) {
        uint32_t ah = aAf + ((ks & 4) ? 4096u : 0u);
        uint32_t bh = aBf + ((ks & 4) ? 8192u : 0u);
        uint32_t xs = (uint32_t)(ks & 3) << 5;
        uint32_t a[4], b[4];
        LDM4(a, ah ^ xs);
        LDM4(b, bh ^ xs);
        b[0] = rnd_bits(b[0]); b[1] = rnd_bits(b[1]);
        b[2] = rnd_bits(b[2]); b[3] = rnd_bits(b[3]);
        mma8(acc[0], a, b[0], b[2]);   // n-rows wn*16 .. +7
        mma8(acc[1], a, b[1], b[3]);   // n-rows wn*16+8 .. +15
    }
}

#define GEMM_SETUP() \
    int tid = threadIdx.x, wid = tid >> 5, lane = tid & 31; \
    int wm = wid >> 2, wn = wid & 3; \
    uint32_t smemS = smem_u32(smem) + ST_OFF; \
    /* A loader (t<128): row t>>2 (0-31), q=t&3 -> 64B contiguous src */ \
    int arow = (tid >> 2) & 31, aq = tid & 3; \
    uint32_t dA[4]; \
    _Pragma("unroll") for (int _j = 0; _j < 4; _j++) \
        dA[_j] = smemS + (uint32_t)(aq >> 1) * 4096 + (uint32_t)arow * 128 + \
                 ((((uint32_t)((aq & 1) * 4 + _j)) ^ (arow & 7)) << 4); \
    /* B loader: row t>>2 (0-63), q=t&3 -> 64B contiguous src, coalesced */ \
    int brow = tid >> 2, bq = tid & 3; \
    uint32_t dB[4]; \
    _Pragma("unroll") for (int _j = 0; _j < 4; _j++) \
        dB[_j] = smemS + 8192 + (uint32_t)(bq >> 1) * 8192 + (uint32_t)brow * 128 + \
                 ((((uint32_t)((bq & 1) * 4 + _j)) ^ (brow & 7)) << 4); \
    /* fragment addresses */ \
    int ls = lane & 7, h3 = (lane >> 3) & 1, h4 = (lane >> 4) & 1; \
    uint32_t amr = (uint32_t)(wm * 16 + 8 * h3 + ls); \
    uint32_t aAf = smemS + amr * 128 + (((uint32_t)h4 ^ ls) << 4); \
    uint32_t bnr = (uint32_t)(wn * 16 + 8 * h3 + ls); \
    uint32_t aBf = smemS + 8192 + bnr * 128 + (((uint32_t)h4 ^ ls) << 4); \
    float acc[2][4]; \
    _Pragma("unroll") for (int _g = 0; _g < 2; _g++) \
    _Pragma("unroll") for (int _q = 0; _q < 4; _q++) acc[_g][_q] = 0.0f;

#define CPA(i, st) do { \
        if (tid < 128) { \
            const float* _s = aglob + (size_t)(i) * 8192; \
            uint32_t _o = (st) * STAGEB; \
            CP16(dA[0] + _o, _s);     CP16(dA[1] + _o, _s + 4); \
            CP16(dA[2] + _o, _s + 8); CP16(dA[3] + _o, _s + 12); \
        } \
    } while (0)

#define CPB(i, st) do { \
        const float* _s = bglob + (size_t)(i) * 64; \
        uint32_t _o = (st) * STAGEB; \
        CP16(dB[0] + _o, _s);     CP16(dB[1] + _o, _s + 4); \
        CP16(dB[2] + _o, _s + 8); CP16(dB[3] + _o, _s + 12); \
    } while (0)

// 3 stages, depth-2 cp.async pipeline, 1 barrier per chunk.
#define GEMM_MAINLOOP(NK) \
    CPA(0, 0); CPB(0, 0); CP_COMMIT(); \
    CPA(1, 1); CPB(1, 1); CP_COMMIT(); \
    { \
        int stc = 0; \
        for (int i = 0; i < (NK); i++) { \
            CP_WAIT1(); \
            __syncthreads(); \
            int st2 = stc + 2; if (st2 >= 3) st2 -= 3; \
            if (i + 2 < (NK)) { CPA(i + 2, st2); CPB(i + 2, st2); } \
            CP_COMMIT(); \
            uint32_t so = (uint32_t)stc * STAGEB; \
            compute_chunk(aAf + so, aBf + so, acc); \
            if (++stc == 3) stc = 0; \
        } \
    }

// ---------------- kernel 3: fc1 GEMM + fused swiglu + coef fold ----------------
// grid (4, 128, NE): x = m-tile (fastest -> concurrent L2 weight reuse),
// y = 32-channel n-tile. B rows 0-31 = up channels n0.., 32-63 = gate INTER+n0..
__global__ void __launch_bounds__(256, 3) fc1_mma(const float* __restrict__ w1) {
    extern __shared__ __align__(1024) char smem[];
    float* coefs = (float*)smem;

    int e   = blockIdx.z;
    int cnt = g_cnt[e];
    int m0g = blockIdx.x * 32;
    if (m0g >= cnt) return;
    int n0  = blockIdx.y * 32;

    GEMM_SETUP();

    if (tid < 32) coefs[tid] = g_coef[e][m0g + tid];   // pads = 0

    // A src: chunk i covers kc 2i, 2i+1; thread: kc 2i+(aq>>1), 64B at (aq&1)*16
    const float* aglob = &g_xg[e][aq >> 1][m0g + arow][(aq & 1) * 16];
    const float* w1e = w1 + (size_t)e * (2 * INTER) * H;
    int wrow = (brow < 32) ? (n0 + brow) : (INTER + n0 + (brow - 32));
    const float* bglob = w1e + (size_t)wrow * H + bq * 16;

    GEMM_MAINLOOP(16);

    // ---- epilogue: exchange via smem, swiglu + coef, tf32-rounded store ----
    __syncthreads();
    float* buf = (float*)(smem + ST_OFF);   // 32 x 68 fp32
    int g0 = lane >> 2, t4 = lane & 3;
#pragma unroll
    for (int rg = 0; rg < 2; rg++) {
        int j  = wn * 16 + rg * 8 + 2 * t4;
        int r0 = wm * 16 + g0;
        buf[r0 * 68 + j]           = acc[rg][0];
        buf[r0 * 68 + j + 1]       = acc[rg][1];
        buf[(r0 + 8) * 68 + j]     = acc[rg][2];
        buf[(r0 + 8) * 68 + j + 1] = acc[rg][3];
    }
    __syncthreads();
    {
        int m  = tid >> 3;           // 0..31
        int cb = (tid & 7) * 4;      // 0..28
        float c = coefs[m];
        const float* row = &buf[m * 68];
        uint4 pk;
        float u0 = row[cb],     gg0 = row[32 + cb];
        float u1 = row[cb + 1], gg1 = row[33 + cb];
        float u2 = row[cb + 2], gg2 = row[34 + cb];
        float u3 = row[cb + 3], gg3 = row[35 + cb];
        pk.x = f2tf(c * (u0 / (1.0f + __expf(-u0))) * gg0);
        pk.y = f2tf(c * (u1 / (1.0f + __expf(-u1))) * gg1);
        pk.z = f2tf(c * (u2 / (1.0f + __expf(-u2))) * gg2);
        pk.w = f2tf(c * (u3 / (1.0f + __expf(-u3))) * gg3);
        *(uint4*)&g_act[e][n0 >> 5][m0g + m][(n0 & 31) + cb] = pk;
    }
}

// ---------------- kernel 4: fc2 GEMM (4-way K-split) + scatter-add ----------------
// grid (4, 64, NE): x = m-tile (fastest), y = n-tile(16 of 64) x k-slice(4).
__global__ void __launch_bounds__(256, 3) fc2_mma(const float* __restrict__ w2,
                                                  float* __restrict__ out) {
    extern __shared__ __align__(1024) char smem[];
    int* toks = (int*)smem;

    int e   = blockIdx.z;
    int cnt = g_cnt[e];
    int m0g = blockIdx.x * 32;
    if (m0g >= cnt) return;
    int n0    = (blockIdx.y >> 2) * 64;
    int kbase = (blockIdx.y & 3) * 1024;

    GEMM_SETUP();

    if (tid < 32) toks[tid] = (m0g + tid < cnt) ? g_tok[e][m0g + tid] : 0;

    const float* aglob = &g_act[e][(kbase >> 5) + (aq >> 1)][m0g + arow][(aq & 1) * 16];
    const float* bglob = w2 + (size_t)e * H * INTER + (size_t)(n0 + brow) * INTER + kbase + bq * 16;

    GEMM_MAINLOOP(16);

    int g0 = lane >> 2, t4 = lane & 3;
    int r0 = wm * 16 + g0;
#pragma unroll
    for (int rg = 0; rg < 2; rg++) {
        int n = n0 + wn * 16 + rg * 8 + 2 * t4;
        if (m0g + r0 < cnt) {
            float* o = out + (size_t)toks[r0] * H + n;
            atomicAdd(o,     acc[rg][0]);
            atomicAdd(o + 1, acc[rg][1]);
        }
        if (m0g + r0 + 8 < cnt) {
            float* o = out + (size_t)toks[r0 + 8] * H + n;
            atomicAdd(o,     acc[rg][2]);
            atomicAdd(o + 1, acc[rg][3]);
        }
    }
}

// ---------------- launch ----------------
extern "C" void kernel_launch(void* const* d_in, const int* in_sizes, int n_in,
                              void* d_out, int out_size) {
    const float* x       = (const float*)d_in[0];   // [128, 1024]
    const float* routing = (const float*)d_in[1];   // [128, 8]
    const float* w1      = (const float*)d_in[2];   // [8, 8192, 1024]
    const float* w2      = (const float*)d_in[3];   // [8, 1024, 4096]
    float* out = (float*)d_out;                     // [128, 1024]

    cudaFuncSetAttribute(fc1_mma, cudaFuncAttributeMaxDynamicSharedMemorySize, SMEM_BYTES);
    cudaFuncSetAttribute(fc2_mma, cudaFuncAttributeMaxDynamicSharedMemorySize, SMEM_BYTES);

    route_kernel<<<1, T>>>(routing);
    gather_x_kernel<<<NE * T, 128>>>(x, out);
    fc1_mma<<<dim3(4, 128, NE), 256, SMEM_BYTES>>>(w1);
    fc2_mma<<<dim3(4, 64, NE), 256, SMEM_BYTES>>>(w2, out);
}